// round 5
// baseline (speedup 1.0000x reference)
#include <cuda_runtime.h>
#include <math.h>

#define NB   32
#define NP   2048
#define KNN  20
#define HDIM 128
#define HID  256
#define NTOT (NB*NP)
#define EPSBN 1e-5f

// ---------------- scratch (static device globals; no allocation) ----------------
__device__ int   g_nbr[NTOT*KNN];
__device__ float g_h0[(size_t)NTOT*HDIM];
__device__ float g_h1[(size_t)NTOT*HDIM];

// ---------------- f32x2 packed-FMA helpers (FFMA2; PTX-only pattern) -----------
__device__ __forceinline__ void ffma2(unsigned long long &d,
                                      unsigned long long a, unsigned long long b) {
    asm("fma.rn.f32x2 %0, %1, %2, %0;" : "+l"(d) : "l"(a), "l"(b));
}
__device__ __forceinline__ unsigned long long pack2(float v) {
    unsigned long long r; asm("mov.b64 %0, {%1, %1};" : "=l"(r) : "f"(v)); return r;
}
__device__ __forceinline__ float2 unpack2(unsigned long long v) {
    float2 f; asm("mov.b64 {%0, %1}, %2;" : "=f"(f.x), "=f"(f.y) : "l"(v)); return f;
}

// ================================================================= kNN =========
// One query per thread; candidates broadcast from SMEM (LDS.128, conflict-free).
// Insert path is position-based: 20 independent compares -> tree-summed insert
// position -> 20 independent predicated shifts. No sequential bubble chain, no
// dynamic register indexing. Ties: '<=' in the position count keeps the earlier
// (lower) index ahead, matching jax.lax.top_k.
#define KBLK 128
__global__ __launch_bounds__(KBLK)
void knn_kernel(const float* __restrict__ x)
{
    __shared__ float4 sc[NP];                 // 32 KB
    const int b    = blockIdx.x >> 4;         // NP/KBLK = 16 tiles per cloud
    const int tile = blockIdx.x & 15;
    const int tid  = threadIdx.x;

    const float* xb = x + (size_t)b*NP*3;
    for (int i = tid; i < NP; i += KBLK) {
        float a0 = xb[i*3+0], a1 = xb[i*3+1], a2 = xb[i*3+2];
        sc[i] = make_float4(a0, a1, a2, a0*a0 + a1*a1 + a2*a2);
    }
    __syncthreads();

    const int q = tile*KBLK + tid;            // local query index in cloud
    const float4 qc = sc[q];

    float d[KNN]; int id[KNN];
#pragma unroll
    for (int j = 0; j < KNN; j++) { d[j] = INFINITY; id[j] = -1; }
    float worst = INFINITY;

#pragma unroll 4
    for (int c = 0; c < NP; c++) {
        float4 cc = sc[c];
        float dot  = qc.x*cc.x + qc.y*cc.y + qc.z*cc.z;
        float dist = qc.w + cc.w - 2.0f*dot;  // matches sq_p + sq_q - 2*dot
        if (dist < worst) {
            // position = #{j : d[j] <= dist}; independent compares, tree sum
            int e0, e1, e2, e3, e4;
            {
                int t[KNN];
#pragma unroll
                for (int j = 0; j < KNN; j++) t[j] = (d[j] <= dist) ? 1 : 0;
                e0 = (t[0]+t[1]) + (t[2]+t[3]);
                e1 = (t[4]+t[5]) + (t[6]+t[7]);
                e2 = (t[8]+t[9]) + (t[10]+t[11]);
                e3 = (t[12]+t[13]) + (t[14]+t[15]);
                e4 = (t[16]+t[17]) + (t[18]+t[19]);
            }
            const int e = (e0+e1) + (e2+e3) + e4;   // 0..19 (dist < d[19])
            // shift [e..18] -> [e+1..19], write (dist,c) at e; all independent
#pragma unroll
            for (int j = KNN-1; j >= 1; j--) {
                float dn = (j > e) ? d[j-1]  : ((j == e) ? dist : d[j]);
                int   in = (j > e) ? id[j-1] : ((j == e) ? c    : id[j]);
                d[j] = dn; id[j] = in;
            }
            if (e == 0) { d[0] = dist; id[0] = c; }
            worst = d[KNN-1];
        }
    }

    int* outp = g_nbr + ((size_t)b*NP + q)*KNN;
#pragma unroll
    for (int j = 0; j < KNN; j++) outp[j] = b*NP + id[j];
}

// ============================================================ transfer =========
__global__ void transfer_kernel(const float* __restrict__ x,
                                const float* __restrict__ Wt,
                                const float* __restrict__ bt)
{
    int idx = blockIdx.x * blockDim.x + threadIdx.x;     // NTOT*HDIM threads
    int n = idx >> 7, f = idx & (HDIM-1);
    float x0 = x[n*3+0], x1 = x[n*3+1], x2 = x[n*3+2];
    g_h0[idx] = bt[f] + x0*Wt[f] + x1*Wt[HDIM+f] + x2*Wt[2*HDIM+f];
}

// ============================================================ GIN layer ========
// Fused: gather-max (self + 20 nbrs) -> GEMM1(128->256)+ReLU -> GEMM2(256->128)
// -> BN (+optional ReLU). ROWS=32 / 512 threads / 112KB smem -> 2 blocks per SM
// (occ 50%), packed fma.rn.f32x2 GEMMs. nbr list overlays the weight buffer.
#define ROWS 32
#define KT   64
#define LTHREADS 512
// s_agg 16K + s_t1 32K + s_w 64K = 114688 B  (s_nbr overlays s_w)
#define GIN_SMEM_BYTES ((ROWS*HDIM + ROWS*HID + KT*HID)*4)

__global__ __launch_bounds__(LTHREADS, 2)
void gin_layer_kernel(const float* __restrict__ hin,
                      const float* __restrict__ W1, const float* __restrict__ b1,
                      const float* __restrict__ W2, const float* __restrict__ b2,
                      const float* __restrict__ gw, const float* __restrict__ bb,
                      const float* __restrict__ rm, const float* __restrict__ rv,
                      float* __restrict__ hout, int relu_out)
{
    extern __shared__ float smem[];
    float* s_agg = smem;                       // [32][128]
    float* s_t1  = s_agg + ROWS*HDIM;          // [32][256]
    float* s_w   = s_t1  + ROWS*HID;           // [64][256] (reused [64][128])
    int*   s_nbr = (int*)s_w;                  // [32][20] overlay (gather phase only)

    const int tid  = threadIdx.x;
    const int row0 = blockIdx.x * ROWS;

    // ---- stage neighbor lists ----
    for (int i = tid; i < ROWS*KNN; i += LTHREADS)
        s_nbr[i] = g_nbr[(size_t)row0*KNN + i];
    __syncthreads();

    // ---- gather-max, float4 rows ----
    {
        const int lf = tid & 31;               // feature quad
        for (int r = tid >> 5; r < ROWS; r += LTHREADS/32) {
            int row = row0 + r;
            float4 m = __ldg((const float4*)&hin[(size_t)row*HDIM + lf*4]);
#pragma unroll 4
            for (int k = 0; k < KNN; k++) {
                int nb = s_nbr[r*KNN + k];
                float4 v = __ldg((const float4*)&hin[(size_t)nb*HDIM + lf*4]);
                m.x = fmaxf(m.x, v.x); m.y = fmaxf(m.y, v.y);
                m.z = fmaxf(m.z, v.z); m.w = fmaxf(m.w, v.w);
            }
            *(float4*)&s_agg[r*HDIM + lf*4] = m;
        }
    }
    __syncthreads();   // also: gather done before s_w overwrites s_nbr

    const int tx = tid & 31;      // column lane (cols tx*4..tx*4+3 of each half)
    const int ty = tid >> 5;      // warp id -> rows ty*2, ty*2+1 (A reads broadcast)

    // ---- GEMM1: t1[32][256] = relu(agg @ W1 + b1), packed f32x2 ----
    unsigned long long acc1[2][4];             // 2 rows x 4 col-pairs (8 cols)
    {
        ulonglong2 bA = *(const ulonglong2*)&b1[tx*4];
        ulonglong2 bB = *(const ulonglong2*)&b1[128 + tx*4];
#pragma unroll
        for (int i = 0; i < 2; i++) {
            acc1[i][0]=bA.x; acc1[i][1]=bA.y; acc1[i][2]=bB.x; acc1[i][3]=bB.y;
        }
    }
    for (int kt = 0; kt < HDIM/KT; kt++) {     // 2 stages
        const float4* src = (const float4*)(W1 + (size_t)kt*KT*HID);
        float4* dst = (float4*)s_w;
        for (int i = tid; i < KT*HID/4; i += LTHREADS) dst[i] = src[i];
        __syncthreads();
#pragma unroll 4
        for (int kk4 = 0; kk4 < KT/4; kk4++) {
            float av[4][2];
#pragma unroll
            for (int i = 0; i < 2; i++) {
                float4 t = *(const float4*)&s_agg[(ty*2+i)*HDIM + kt*KT + kk4*4];
                av[0][i]=t.x; av[1][i]=t.y; av[2][i]=t.z; av[3][i]=t.w;
            }
#pragma unroll
            for (int u = 0; u < 4; u++) {
                int kk = kk4*4 + u;
                ulonglong2 wA = *(const ulonglong2*)&s_w[kk*HID + tx*4];
                ulonglong2 wB = *(const ulonglong2*)&s_w[kk*HID + 128 + tx*4];
#pragma unroll
                for (int i = 0; i < 2; i++) {
                    unsigned long long pa = pack2(av[u][i]);
                    ffma2(acc1[i][0], pa, wA.x);
                    ffma2(acc1[i][1], pa, wA.y);
                    ffma2(acc1[i][2], pa, wB.x);
                    ffma2(acc1[i][3], pa, wB.y);
                }
            }
        }
        __syncthreads();
    }
#pragma unroll
    for (int i = 0; i < 2; i++) {
        float2 p0 = unpack2(acc1[i][0]), p1 = unpack2(acc1[i][1]);
        float2 p2 = unpack2(acc1[i][2]), p3 = unpack2(acc1[i][3]);
        float4 v0 = make_float4(fmaxf(p0.x,0.f), fmaxf(p0.y,0.f),
                                fmaxf(p1.x,0.f), fmaxf(p1.y,0.f));
        float4 v1 = make_float4(fmaxf(p2.x,0.f), fmaxf(p2.y,0.f),
                                fmaxf(p3.x,0.f), fmaxf(p3.y,0.f));
        *(float4*)&s_t1[(ty*2+i)*HID + tx*4]       = v0;
        *(float4*)&s_t1[(ty*2+i)*HID + 128 + tx*4] = v1;
    }
    __syncthreads();

    // ---- GEMM2: out[32][128] = t1 @ W2 + b2, packed f32x2 ----
    unsigned long long acc2[2][2];             // 2 rows x 2 col-pairs (4 cols)
    {
        ulonglong2 b2v = *(const ulonglong2*)&b2[tx*4];
#pragma unroll
        for (int i = 0; i < 2; i++) { acc2[i][0]=b2v.x; acc2[i][1]=b2v.y; }
    }
    for (int kt = 0; kt < HID/KT; kt++) {      // 4 stages
        const float4* src = (const float4*)(W2 + (size_t)kt*KT*HDIM);
        float4* dst = (float4*)s_w;
        for (int i = tid; i < KT*HDIM/4; i += LTHREADS) dst[i] = src[i];
        __syncthreads();
#pragma unroll 4
        for (int kk4 = 0; kk4 < KT/4; kk4++) {
            float av[4][2];
#pragma unroll
            for (int i = 0; i < 2; i++) {
                float4 t = *(const float4*)&s_t1[(ty*2+i)*HID + kt*KT + kk4*4];
                av[0][i]=t.x; av[1][i]=t.y; av[2][i]=t.z; av[3][i]=t.w;
            }
#pragma unroll
            for (int u = 0; u < 4; u++) {
                int kk = kk4*4 + u;
                ulonglong2 w = *(const ulonglong2*)&s_w[kk*HDIM + tx*4];
#pragma unroll
                for (int i = 0; i < 2; i++) {
                    unsigned long long pa = pack2(av[u][i]);
                    ffma2(acc2[i][0], pa, w.x);
                    ffma2(acc2[i][1], pa, w.y);
                }
            }
        }
        __syncthreads();
    }

    // ---- BN (+optional ReLU), coalesced float4 stores ----
    {
        float4 g4  = *(const float4*)&gw[tx*4];
        float4 be4 = *(const float4*)&bb[tx*4];
        float4 rm4 = *(const float4*)&rm[tx*4];
        float4 rv4 = *(const float4*)&rv[tx*4];
        float s0 = g4.x*rsqrtf(rv4.x+EPSBN), s1 = g4.y*rsqrtf(rv4.y+EPSBN);
        float s2 = g4.z*rsqrtf(rv4.z+EPSBN), s3 = g4.w*rsqrtf(rv4.w+EPSBN);
#pragma unroll
        for (int i = 0; i < 2; i++) {
            float2 p0 = unpack2(acc2[i][0]), p1 = unpack2(acc2[i][1]);
            float4 v;
            v.x = s0*(p0.x-rm4.x) + be4.x;
            v.y = s1*(p0.y-rm4.y) + be4.y;
            v.z = s2*(p1.x-rm4.z) + be4.z;
            v.w = s3*(p1.y-rm4.w) + be4.w;
            if (relu_out) {
                v.x = fmaxf(v.x, 0.f); v.y = fmaxf(v.y, 0.f);
                v.z = fmaxf(v.z, 0.f); v.w = fmaxf(v.w, 0.f);
            }
            *(float4*)&hout[(size_t)(row0 + ty*2 + i)*HDIM + tx*4] = v;
        }
    }
}

// ================================================================ launch =======
extern "C" void kernel_launch(void* const* d_in, const int* in_sizes, int n_in,
                              void* d_out, int out_size)
{
    const float* x    = (const float*)d_in[0];
    // d_in[1] = batch (unused: equal-size clouds by construction)
    const float* Wt   = (const float*)d_in[2];
    const float* bt   = (const float*)d_in[3];
    const float* W1_0 = (const float*)d_in[4];
    const float* b1_0 = (const float*)d_in[5];
    const float* W2_0 = (const float*)d_in[6];
    const float* b2_0 = (const float*)d_in[7];
    const float* g0   = (const float*)d_in[8];
    const float* be0  = (const float*)d_in[9];
    const float* rm0  = (const float*)d_in[10];
    const float* rv0  = (const float*)d_in[11];
    const float* W1_1 = (const float*)d_in[12];
    const float* b1_1 = (const float*)d_in[13];
    const float* W2_1 = (const float*)d_in[14];
    const float* b2_1 = (const float*)d_in[15];
    const float* g1   = (const float*)d_in[16];
    const float* be1  = (const float*)d_in[17];
    const float* rm1  = (const float*)d_in[18];
    const float* rv1  = (const float*)d_in[19];
    float* out = (float*)d_out;

    cudaFuncSetAttribute(gin_layer_kernel,
                         cudaFuncAttributeMaxDynamicSharedMemorySize, GIN_SMEM_BYTES);

    void *p_h0, *p_h1;
    cudaGetSymbolAddress(&p_h0, g_h0);
    cudaGetSymbolAddress(&p_h1, g_h1);

    knn_kernel<<<NB*(NP/KBLK), KBLK>>>(x);
    transfer_kernel<<<(NTOT*HDIM)/256, 256>>>(x, Wt, bt);

    gin_layer_kernel<<<NTOT/ROWS, LTHREADS, GIN_SMEM_BYTES>>>(
        (const float*)p_h0, W1_0, b1_0, W2_0, b2_0, g0, be0, rm0, rv0,
        (float*)p_h1, /*relu_out=*/1);

    gin_layer_kernel<<<NTOT/ROWS, LTHREADS, GIN_SMEM_BYTES>>>(
        (const float*)p_h1, W1_1, b1_1, W2_1, b2_1, g1, be1, rm1, rv1,
        out, /*relu_out=*/0);
}

// round 6
// speedup vs baseline: 1.3728x; 1.3728x over previous
#include <cuda_runtime.h>
#include <math.h>

#define NB   32
#define NP   2048
#define KNN  20
#define HDIM 128
#define HID  256
#define NTOT (NB*NP)
#define EPSBN 1e-5f

// ---------------- scratch (static device globals; no allocation) ----------------
__device__ int   g_nbr[NTOT*KNN];
__device__ float g_h0[(size_t)NTOT*HDIM];
__device__ float g_h1[(size_t)NTOT*HDIM];

// ---------------- f32x2 packed-FMA helpers (FFMA2; PTX-only pattern) -----------
__device__ __forceinline__ void ffma2(unsigned long long &d,
                                      unsigned long long a, unsigned long long b) {
    asm("fma.rn.f32x2 %0, %1, %2, %0;" : "+l"(d) : "l"(a), "l"(b));
}
__device__ __forceinline__ unsigned long long pack2(float v) {
    unsigned long long r; asm("mov.b64 %0, {%1, %1};" : "=l"(r) : "f"(v)); return r;
}
__device__ __forceinline__ float2 unpack2(unsigned long long v) {
    float2 f; asm("mov.b64 {%0, %1}, %2;" : "=f"(f.x), "=f"(f.y) : "l"(v)); return f;
}

// ================================================================= kNN =========
// R3-proven version: one query per thread; candidates broadcast from SMEM
// (LDS.128 conflict-free). Filtered sorted bubble-insert (predicated swaps).
// Ties: strict '<' keeps earlier (lower) index, matching jax.lax.top_k.
#define KBLK 128
__global__ __launch_bounds__(KBLK)
void knn_kernel(const float* __restrict__ x)
{
    __shared__ float4 sc[NP];                 // 32 KB
    const int b    = blockIdx.x >> 4;         // NP/KBLK = 16 tiles per cloud
    const int tile = blockIdx.x & 15;
    const int tid  = threadIdx.x;

    const float* xb = x + (size_t)b*NP*3;
    for (int i = tid; i < NP; i += KBLK) {
        float a0 = xb[i*3+0], a1 = xb[i*3+1], a2 = xb[i*3+2];
        sc[i] = make_float4(a0, a1, a2, a0*a0 + a1*a1 + a2*a2);
    }
    __syncthreads();

    const int q = tile*KBLK + tid;            // local query index in cloud
    const float4 qc = sc[q];

    float d[KNN]; int id[KNN];
#pragma unroll
    for (int j = 0; j < KNN; j++) { d[j] = INFINITY; id[j] = -1; }
    float worst = INFINITY;

#pragma unroll 2
    for (int c = 0; c < NP; c++) {
        float4 cc = sc[c];
        float dot  = qc.x*cc.x + qc.y*cc.y + qc.z*cc.z;
        float dist = qc.w + cc.w - 2.0f*dot;  // matches sq_p + sq_q - 2*dot
        if (dist < worst) {
            float vd = dist; int vi = c;
#pragma unroll
            for (int j = 0; j < KNN; j++) {   // bubble-insert, keeps ascending
                if (vd < d[j]) {
                    float td = d[j]; int ti = id[j];
                    d[j] = vd; id[j] = vi; vd = td; vi = ti;
                }
            }
            worst = d[KNN-1];
        }
    }

    int* outp = g_nbr + ((size_t)b*NP + q)*KNN;
#pragma unroll
    for (int j = 0; j < KNN; j++) outp[j] = b*NP + id[j];
}

// ============================================================ transfer =========
__global__ void transfer_kernel(const float* __restrict__ x,
                                const float* __restrict__ Wt,
                                const float* __restrict__ bt)
{
    int idx = blockIdx.x * blockDim.x + threadIdx.x;     // NTOT*HDIM threads
    int n = idx >> 7, f = idx & (HDIM-1);
    float x0 = x[n*3+0], x1 = x[n*3+1], x2 = x[n*3+2];
    g_h0[idx] = bt[f] + x0*Wt[f] + x1*Wt[HDIM+f] + x2*Wt[2*HDIM+f];
}

// ============================================================ GIN layer ========
// Fused: gather-max (self + 20 nbrs) -> GEMM1(128->256)+ReLU -> GEMM2(256->128)
// -> BN (+optional ReLU).
// ROWS=64 / 512 threads: 4 rows/thread keeps the W-LDS : FFMA2 crossbar ratio
// balanced. SMEM = s_agg(32K) + s_w(64K) = 96K -> 2 blocks/SM (occ 50%).
// t1 has NO dedicated buffer: cols 0-127 overwrite s_agg (dead after GEMM1),
// cols 128-255 live in the upper half of s_w (GEMM2 stages W2 in lower 32K).
#define ROWS 64
#define KT   64
#define LTHREADS 512
#define GIN_SMEM_BYTES ((ROWS*HDIM + KT*HID)*4)    // 98304

__global__ __launch_bounds__(LTHREADS, 2)
void gin_layer_kernel(const float* __restrict__ hin,
                      const float* __restrict__ W1, const float* __restrict__ b1,
                      const float* __restrict__ W2, const float* __restrict__ b2,
                      const float* __restrict__ gw, const float* __restrict__ bb,
                      const float* __restrict__ rm, const float* __restrict__ rv,
                      float* __restrict__ hout, int relu_out)
{
    extern __shared__ float smem[];
    float* s_agg = smem;                       // [64][128]  (later: t1 cols 0-127)
    float* s_w   = s_agg + ROWS*HDIM;          // [64][256]  (upper 32K: t1 cols 128-255)
    float* s_t1b = s_w + 8192;                 // t1 high half, row stride 128
    int*   s_nbr = (int*)s_w;                  // [64][20] overlay (gather phase only)

    const int tid  = threadIdx.x;
    const int row0 = blockIdx.x * ROWS;

    // ---- stage neighbor lists ----
    for (int i = tid; i < ROWS*KNN; i += LTHREADS)
        s_nbr[i] = g_nbr[(size_t)row0*KNN + i];
    __syncthreads();

    // ---- gather-max, float4 rows ----
    {
        const int lf = tid & 31;               // feature quad
        for (int r = tid >> 5; r < ROWS; r += LTHREADS/32) {
            int row = row0 + r;
            float4 m = __ldg((const float4*)&hin[(size_t)row*HDIM + lf*4]);
#pragma unroll 4
            for (int k = 0; k < KNN; k++) {
                int nb = s_nbr[r*KNN + k];
                float4 v = __ldg((const float4*)&hin[(size_t)nb*HDIM + lf*4]);
                m.x = fmaxf(m.x, v.x); m.y = fmaxf(m.y, v.y);
                m.z = fmaxf(m.z, v.z); m.w = fmaxf(m.w, v.w);
            }
            *(float4*)&s_agg[r*HDIM + lf*4] = m;
        }
    }
    __syncthreads();   // gather done before s_w overwrites s_nbr

    const int tx = tid & 31;      // column lane (cols tx*4..+3 of each 128-half)
    const int ty = tid >> 5;      // warp id -> rows ty*4..ty*4+3 (A reads broadcast)

    // ---- GEMM1: t1[64][256] = relu(agg @ W1 + b1), packed f32x2 ----
    unsigned long long acc1[4][4];             // 4 rows x 4 col-pairs (8 cols)
    {
        ulonglong2 bA = *(const ulonglong2*)&b1[tx*4];
        ulonglong2 bB = *(const ulonglong2*)&b1[128 + tx*4];
#pragma unroll
        for (int i = 0; i < 4; i++) {
            acc1[i][0]=bA.x; acc1[i][1]=bA.y; acc1[i][2]=bB.x; acc1[i][3]=bB.y;
        }
    }
    for (int kt = 0; kt < HDIM/KT; kt++) {     // 2 stages
        const float4* src = (const float4*)(W1 + (size_t)kt*KT*HID);
        float4* dst = (float4*)s_w;
        for (int i = tid; i < KT*HID/4; i += LTHREADS) dst[i] = src[i];
        __syncthreads();
        const float* abase = s_agg + ty*4*HDIM + kt*KT;
#pragma unroll 4
        for (int kk = 0; kk < KT; kk++) {
            ulonglong2 wA = *(const ulonglong2*)&s_w[kk*HID + tx*4];
            ulonglong2 wB = *(const ulonglong2*)&s_w[kk*HID + 128 + tx*4];
#pragma unroll
            for (int i = 0; i < 4; i++) {
                unsigned long long pa = pack2(abase[i*HDIM + kk]);  // LDS broadcast
                ffma2(acc1[i][0], pa, wA.x);
                ffma2(acc1[i][1], pa, wA.y);
                ffma2(acc1[i][2], pa, wB.x);
                ffma2(acc1[i][3], pa, wB.y);
            }
        }
        __syncthreads();
    }
    // write t1 (ReLU): low half over s_agg, high half into s_w upper 32K
#pragma unroll
    for (int i = 0; i < 4; i++) {
        float2 p0 = unpack2(acc1[i][0]), p1 = unpack2(acc1[i][1]);
        float2 p2 = unpack2(acc1[i][2]), p3 = unpack2(acc1[i][3]);
        float4 v0 = make_float4(fmaxf(p0.x,0.f), fmaxf(p0.y,0.f),
                                fmaxf(p1.x,0.f), fmaxf(p1.y,0.f));
        float4 v1 = make_float4(fmaxf(p2.x,0.f), fmaxf(p2.y,0.f),
                                fmaxf(p3.x,0.f), fmaxf(p3.y,0.f));
        *(float4*)&s_agg[(ty*4+i)*HDIM + tx*4] = v0;   // t1 cols [0,128)
        *(float4*)&s_t1b[(ty*4+i)*HDIM + tx*4] = v1;   // t1 cols [128,256)
    }
    __syncthreads();

    // ---- GEMM2: out[64][128] = t1 @ W2 + b2, packed f32x2 ----
    unsigned long long acc2[4][2];             // 4 rows x 2 col-pairs (4 cols)
    {
        ulonglong2 b2v = *(const ulonglong2*)&b2[tx*4];
#pragma unroll
        for (int i = 0; i < 4; i++) { acc2[i][0]=b2v.x; acc2[i][1]=b2v.y; }
    }
    for (int kt = 0; kt < HID/KT; kt++) {      // 4 stages; W2 chunk -> s_w lower 32K
        const float4* src = (const float4*)(W2 + (size_t)kt*KT*HDIM);
        float4* dst = (float4*)s_w;
        for (int i = tid; i < KT*HDIM/4; i += LTHREADS) dst[i] = src[i];
        __syncthreads();
        // t1 source for this K-chunk: kt 0,1 -> s_agg; kt 2,3 -> s_w upper half
        const float* tbase = ((kt < 2) ? (s_agg + kt*KT) : (s_t1b + (kt-2)*KT))
                             + ty*4*HDIM;
#pragma unroll 4
        for (int kk = 0; kk < KT; kk++) {
            ulonglong2 w = *(const ulonglong2*)&s_w[kk*HDIM + tx*4];
#pragma unroll
            for (int i = 0; i < 4; i++) {
                unsigned long long pa = pack2(tbase[i*HDIM + kk]); // LDS broadcast
                ffma2(acc2[i][0], pa, w.x);
                ffma2(acc2[i][1], pa, w.y);
            }
        }
        __syncthreads();
    }

    // ---- BN (+optional ReLU), coalesced float4 stores ----
    {
        float4 g4  = *(const float4*)&gw[tx*4];
        float4 be4 = *(const float4*)&bb[tx*4];
        float4 rm4 = *(const float4*)&rm[tx*4];
        float4 rv4 = *(const float4*)&rv[tx*4];
        float s0 = g4.x*rsqrtf(rv4.x+EPSBN), s1 = g4.y*rsqrtf(rv4.y+EPSBN);
        float s2 = g4.z*rsqrtf(rv4.z+EPSBN), s3 = g4.w*rsqrtf(rv4.w+EPSBN);
#pragma unroll
        for (int i = 0; i < 4; i++) {
            float2 p0 = unpack2(acc2[i][0]), p1 = unpack2(acc2[i][1]);
            float4 v;
            v.x = s0*(p0.x-rm4.x) + be4.x;
            v.y = s1*(p0.y-rm4.y) + be4.y;
            v.z = s2*(p1.x-rm4.z) + be4.z;
            v.w = s3*(p1.y-rm4.w) + be4.w;
            if (relu_out) {
                v.x = fmaxf(v.x, 0.f); v.y = fmaxf(v.y, 0.f);
                v.z = fmaxf(v.z, 0.f); v.w = fmaxf(v.w, 0.f);
            }
            *(float4*)&hout[(size_t)(row0 + ty*4 + i)*HDIM + tx*4] = v;
        }
    }
}

// ================================================================ launch =======
extern "C" void kernel_launch(void* const* d_in, const int* in_sizes, int n_in,
                              void* d_out, int out_size)
{
    const float* x    = (const float*)d_in[0];
    // d_in[1] = batch (unused: equal-size clouds by construction)
    const float* Wt   = (const float*)d_in[2];
    const float* bt   = (const float*)d_in[3];
    const float* W1_0 = (const float*)d_in[4];
    const float* b1_0 = (const float*)d_in[5];
    const float* W2_0 = (const float*)d_in[6];
    const float* b2_0 = (const float*)d_in[7];
    const float* g0   = (const float*)d_in[8];
    const float* be0  = (const float*)d_in[9];
    const float* rm0  = (const float*)d_in[10];
    const float* rv0  = (const float*)d_in[11];
    const float* W1_1 = (const float*)d_in[12];
    const float* b1_1 = (const float*)d_in[13];
    const float* W2_1 = (const float*)d_in[14];
    const float* b2_1 = (const float*)d_in[15];
    const float* g1   = (const float*)d_in[16];
    const float* be1  = (const float*)d_in[17];
    const float* rm1  = (const float*)d_in[18];
    const float* rv1  = (const float*)d_in[19];
    float* out = (float*)d_out;

    cudaFuncSetAttribute(gin_layer_kernel,
                         cudaFuncAttributeMaxDynamicSharedMemorySize, GIN_SMEM_BYTES);

    void *p_h0, *p_h1;
    cudaGetSymbolAddress(&p_h0, g_h0);
    cudaGetSymbolAddress(&p_h1, g_h1);

    knn_kernel<<<NB*(NP/KBLK), KBLK>>>(x);
    transfer_kernel<<<(NTOT*HDIM)/256, 256>>>(x, Wt, bt);

    gin_layer_kernel<<<NTOT/ROWS, LTHREADS, GIN_SMEM_BYTES>>>(
        (const float*)p_h0, W1_0, b1_0, W2_0, b2_0, g0, be0, rm0, rv0,
        (float*)p_h1, /*relu_out=*/1);

    gin_layer_kernel<<<NTOT/ROWS, LTHREADS, GIN_SMEM_BYTES>>>(
        (const float*)p_h1, W1_1, b1_1, W2_1, b2_1, g1, be1, rm1, rv1,
        out, /*relu_out=*/0);
}

// round 8
// speedup vs baseline: 1.9257x; 1.4028x over previous
#include <cuda_runtime.h>
#include <math.h>

#define NB   32
#define NP   2048
#define KNN  20
#define HDIM 128
#define HID  256
#define NTOT (NB*NP)
#define EPSBN 1e-5f

// ---------------- scratch (static device globals; no allocation) ----------------
__device__ int   g_nbr[NTOT*KNN];
__device__ float g_h0[(size_t)NTOT*HDIM];
__device__ float g_h1[(size_t)NTOT*HDIM];

// ---------------- f32x2 packed-FMA helpers (FFMA2; PTX-only pattern) -----------
__device__ __forceinline__ void ffma2(unsigned long long &d,
                                      unsigned long long a, unsigned long long b) {
    asm("fma.rn.f32x2 %0, %1, %2, %0;" : "+l"(d) : "l"(a), "l"(b));
}
__device__ __forceinline__ unsigned long long pack2(float v) {
    unsigned long long r; asm("mov.b64 %0, {%1, %1};" : "=l"(r) : "f"(v)); return r;
}
__device__ __forceinline__ float2 unpack2(unsigned long long v) {
    float2 f; asm("mov.b64 {%0, %1}, %2;" : "=f"(f.x), "=f"(f.y) : "l"(v)); return f;
}

// ================================================================= kNN =========
// One query per thread; candidates broadcast from SMEM (LDS.128 conflict-free).
// Deferred-insert: passing candidate INDICES are pushed to a per-thread SMEM
// stack (1 predicated STS). The expensive sorted bubble-insert runs only inside
// synchronized drains (dist recomputed from the sc[] cache), cutting warp-level
// bubble executions ~1385 -> ~200. The stale 'worst' threshold only over-admits
// (worst is monotone decreasing), so exact top-20 membership is preserved;
// downstream max-aggregation is order-invariant.
// SMEM is DYNAMIC (48 KB > 48K static limit would be hit with float stacks).
#define KBLK 128
#define KCAP 32
#define KNN_SMEM_BYTES (NP*16 + KCAP*KBLK*4)   // sc 32K + sbi 16K = 49152
__global__ __launch_bounds__(KBLK)
void knn_kernel(const float* __restrict__ x)
{
    extern __shared__ float4 sc[];            // [NP] candidate cache (32 KB)
    int* sbi = (int*)(sc + NP);               // [KCAP][KBLK] id stacks (16 KB)
    const int b    = blockIdx.x >> 4;         // NP/KBLK = 16 tiles per cloud
    const int tile = blockIdx.x & 15;
    const int tid  = threadIdx.x;

    const float* xb = x + (size_t)b*NP*3;
    for (int i = tid; i < NP; i += KBLK) {
        float a0 = xb[i*3+0], a1 = xb[i*3+1], a2 = xb[i*3+2];
        sc[i] = make_float4(a0, a1, a2, a0*a0 + a1*a1 + a2*a2);
    }
    __syncthreads();

    const int q = tile*KBLK + tid;            // local query index in cloud
    const float4 qc = sc[q];

    float d[KNN]; int id[KNN];
#pragma unroll
    for (int j = 0; j < KNN; j++) { d[j] = INFINITY; id[j] = -1; }
    float worst = INFINITY;
    int cnt = 0;

    for (int c0 = 0; c0 < NP; c0 += 4) {
#pragma unroll
        for (int u = 0; u < 4; u++) {
            int c = c0 + u;
            float4 cc = sc[c];
            float dot  = qc.x*cc.x + qc.y*cc.y + qc.z*cc.z;
            float dist = qc.w + cc.w - 2.0f*dot;   // matches sq_p + sq_q - 2*dot
            if (dist < worst) {                    // cheap predicated push
                sbi[cnt*KBLK + tid] = c;
                cnt++;
            }
        }
        // drain when any lane is within 4 of full (<=4 pushes between checks)
        if (__any_sync(0xffffffffu, cnt >= KCAP-4)) {
            for (int j = 0; ; j++) {
                if (!__any_sync(0xffffffffu, j < cnt)) break;
                float dd = INFINITY; int ii = 0;
                if (j < cnt) {
                    ii = sbi[j*KBLK + tid];
                    float4 cc = sc[ii];
                    float dot = qc.x*cc.x + qc.y*cc.y + qc.z*cc.z;
                    dd = qc.w + cc.w - 2.0f*dot;
                }
                if (dd < worst) {
                    float vd = dd; int vi = ii;
#pragma unroll
                    for (int t = 0; t < KNN; t++) {     // bubble-insert, ascending
                        if (vd < d[t]) {
                            float td = d[t]; int ti = id[t];
                            d[t] = vd; id[t] = vi; vd = td; vi = ti;
                        }
                    }
                    worst = d[KNN-1];
                }
            }
            cnt = 0;
        }
    }
    // final drain
    for (int j = 0; ; j++) {
        if (!__any_sync(0xffffffffu, j < cnt)) break;
        float dd = INFINITY; int ii = 0;
        if (j < cnt) {
            ii = sbi[j*KBLK + tid];
            float4 cc = sc[ii];
            float dot = qc.x*cc.x + qc.y*cc.y + qc.z*cc.z;
            dd = qc.w + cc.w - 2.0f*dot;
        }
        if (dd < worst) {
            float vd = dd; int vi = ii;
#pragma unroll
            for (int t = 0; t < KNN; t++) {
                if (vd < d[t]) {
                    float td = d[t]; int ti = id[t];
                    d[t] = vd; id[t] = vi; vd = td; vi = ti;
                }
            }
            worst = d[KNN-1];
        }
    }

    int* outp = g_nbr + ((size_t)b*NP + q)*KNN;
#pragma unroll
    for (int j = 0; j < KNN; j++) outp[j] = b*NP + id[j];
}

// ============================================================ transfer =========
__global__ void transfer_kernel(const float* __restrict__ x,
                                const float* __restrict__ Wt,
                                const float* __restrict__ bt)
{
    int idx = blockIdx.x * blockDim.x + threadIdx.x;     // NTOT*HDIM threads
    int n = idx >> 7, f = idx & (HDIM-1);
    float x0 = x[n*3+0], x1 = x[n*3+1], x2 = x[n*3+2];
    g_h0[idx] = bt[f] + x0*Wt[f] + x1*Wt[HDIM+f] + x2*Wt[2*HDIM+f];
}

// ============================================================ GIN layer ========
// (unchanged from R6 win: 241us/layer)
// Fused: gather-max (self + 20 nbrs) -> GEMM1(128->256)+ReLU -> GEMM2(256->128)
// -> BN (+optional ReLU). ROWS=64 / 512 threads: 4 rows/thread keeps the
// W-LDS : FFMA2 crossbar ratio balanced. SMEM = 96K -> 2 blocks/SM (occ 50%).
// t1 cols 0-127 overwrite s_agg; cols 128-255 live in the upper half of s_w.
#define ROWS 64
#define KT   64
#define LTHREADS 512
#define GIN_SMEM_BYTES ((ROWS*HDIM + KT*HID)*4)    // 98304

__global__ __launch_bounds__(LTHREADS, 2)
void gin_layer_kernel(const float* __restrict__ hin,
                      const float* __restrict__ W1, const float* __restrict__ b1,
                      const float* __restrict__ W2, const float* __restrict__ b2,
                      const float* __restrict__ gw, const float* __restrict__ bb,
                      const float* __restrict__ rm, const float* __restrict__ rv,
                      float* __restrict__ hout, int relu_out)
{
    extern __shared__ float smem[];
    float* s_agg = smem;                       // [64][128]  (later: t1 cols 0-127)
    float* s_w   = s_agg + ROWS*HDIM;          // [64][256]  (upper 32K: t1 cols 128-255)
    float* s_t1b = s_w + 8192;                 // t1 high half, row stride 128
    int*   s_nbr = (int*)s_w;                  // [64][20] overlay (gather phase only)

    const int tid  = threadIdx.x;
    const int row0 = blockIdx.x * ROWS;

    for (int i = tid; i < ROWS*KNN; i += LTHREADS)
        s_nbr[i] = g_nbr[(size_t)row0*KNN + i];
    __syncthreads();

    {
        const int lf = tid & 31;               // feature quad
        for (int r = tid >> 5; r < ROWS; r += LTHREADS/32) {
            int row = row0 + r;
            float4 m = __ldg((const float4*)&hin[(size_t)row*HDIM + lf*4]);
#pragma unroll 4
            for (int k = 0; k < KNN; k++) {
                int nb = s_nbr[r*KNN + k];
                float4 v = __ldg((const float4*)&hin[(size_t)nb*HDIM + lf*4]);
                m.x = fmaxf(m.x, v.x); m.y = fmaxf(m.y, v.y);
                m.z = fmaxf(m.z, v.z); m.w = fmaxf(m.w, v.w);
            }
            *(float4*)&s_agg[r*HDIM + lf*4] = m;
        }
    }
    __syncthreads();

    const int tx = tid & 31;
    const int ty = tid >> 5;

    // ---- GEMM1 ----
    unsigned long long acc1[4][4];
    {
        ulonglong2 bA = *(const ulonglong2*)&b1[tx*4];
        ulonglong2 bB = *(const ulonglong2*)&b1[128 + tx*4];
#pragma unroll
        for (int i = 0; i < 4; i++) {
            acc1[i][0]=bA.x; acc1[i][1]=bA.y; acc1[i][2]=bB.x; acc1[i][3]=bB.y;
        }
    }
    for (int kt = 0; kt < HDIM/KT; kt++) {
        const float4* src = (const float4*)(W1 + (size_t)kt*KT*HID);
        float4* dst = (float4*)s_w;
        for (int i = tid; i < KT*HID/4; i += LTHREADS) dst[i] = src[i];
        __syncthreads();
        const float* abase = s_agg + ty*4*HDIM + kt*KT;
#pragma unroll 4
        for (int kk = 0; kk < KT; kk++) {
            ulonglong2 wA = *(const ulonglong2*)&s_w[kk*HID + tx*4];
            ulonglong2 wB = *(const ulonglong2*)&s_w[kk*HID + 128 + tx*4];
#pragma unroll
            for (int i = 0; i < 4; i++) {
                unsigned long long pa = pack2(abase[i*HDIM + kk]);
                ffma2(acc1[i][0], pa, wA.x);
                ffma2(acc1[i][1], pa, wA.y);
                ffma2(acc1[i][2], pa, wB.x);
                ffma2(acc1[i][3], pa, wB.y);
            }
        }
        __syncthreads();
    }
#pragma unroll
    for (int i = 0; i < 4; i++) {
        float2 p0 = unpack2(acc1[i][0]), p1 = unpack2(acc1[i][1]);
        float2 p2 = unpack2(acc1[i][2]), p3 = unpack2(acc1[i][3]);
        float4 v0 = make_float4(fmaxf(p0.x,0.f), fmaxf(p0.y,0.f),
                                fmaxf(p1.x,0.f), fmaxf(p1.y,0.f));
        float4 v1 = make_float4(fmaxf(p2.x,0.f), fmaxf(p2.y,0.f),
                                fmaxf(p3.x,0.f), fmaxf(p3.y,0.f));
        *(float4*)&s_agg[(ty*4+i)*HDIM + tx*4] = v0;
        *(float4*)&s_t1b[(ty*4+i)*HDIM + tx*4] = v1;
    }
    __syncthreads();

    // ---- GEMM2 ----
    unsigned long long acc2[4][2];
    {
        ulonglong2 b2v = *(const ulonglong2*)&b2[tx*4];
#pragma unroll
        for (int i = 0; i < 4; i++) { acc2[i][0]=b2v.x; acc2[i][1]=b2v.y; }
    }
    for (int kt = 0; kt < HID/KT; kt++) {
        const float4* src = (const float4*)(W2 + (size_t)kt*KT*HDIM);
        float4* dst = (float4*)s_w;
        for (int i = tid; i < KT*HDIM/4; i += LTHREADS) dst[i] = src[i];
        __syncthreads();
        const float* tbase = ((kt < 2) ? (s_agg + kt*KT) : (s_t1b + (kt-2)*KT))
                             + ty*4*HDIM;
#pragma unroll 4
        for (int kk = 0; kk < KT; kk++) {
            ulonglong2 w = *(const ulonglong2*)&s_w[kk*HDIM + tx*4];
#pragma unroll
            for (int i = 0; i < 4; i++) {
                unsigned long long pa = pack2(tbase[i*HDIM + kk]);
                ffma2(acc2[i][0], pa, w.x);
                ffma2(acc2[i][1], pa, w.y);
            }
        }
        __syncthreads();
    }

    // ---- BN (+optional ReLU) ----
    {
        float4 g4  = *(const float4*)&gw[tx*4];
        float4 be4 = *(const float4*)&bb[tx*4];
        float4 rm4 = *(const float4*)&rm[tx*4];
        float4 rv4 = *(const float4*)&rv[tx*4];
        float s0 = g4.x*rsqrtf(rv4.x+EPSBN), s1 = g4.y*rsqrtf(rv4.y+EPSBN);
        float s2 = g4.z*rsqrtf(rv4.z+EPSBN), s3 = g4.w*rsqrtf(rv4.w+EPSBN);
#pragma unroll
        for (int i = 0; i < 4; i++) {
            float2 p0 = unpack2(acc2[i][0]), p1 = unpack2(acc2[i][1]);
            float4 v;
            v.x = s0*(p0.x-rm4.x) + be4.x;
            v.y = s1*(p0.y-rm4.y) + be4.y;
            v.z = s2*(p1.x-rm4.z) + be4.z;
            v.w = s3*(p1.y-rm4.w) + be4.w;
            if (relu_out) {
                v.x = fmaxf(v.x, 0.f); v.y = fmaxf(v.y, 0.f);
                v.z = fmaxf(v.z, 0.f); v.w = fmaxf(v.w, 0.f);
            }
            *(float4*)&hout[(size_t)(row0 + ty*4 + i)*HDIM + tx*4] = v;
        }
    }
}

// ================================================================ launch =======
extern "C" void kernel_launch(void* const* d_in, const int* in_sizes, int n_in,
                              void* d_out, int out_size)
{
    const float* x    = (const float*)d_in[0];
    // d_in[1] = batch (unused: equal-size clouds by construction)
    const float* Wt   = (const float*)d_in[2];
    const float* bt   = (const float*)d_in[3];
    const float* W1_0 = (const float*)d_in[4];
    const float* b1_0 = (const float*)d_in[5];
    const float* W2_0 = (const float*)d_in[6];
    const float* b2_0 = (const float*)d_in[7];
    const float* g0   = (const float*)d_in[8];
    const float* be0  = (const float*)d_in[9];
    const float* rm0  = (const float*)d_in[10];
    const float* rv0  = (const float*)d_in[11];
    const float* W1_1 = (const float*)d_in[12];
    const float* b1_1 = (const float*)d_in[13];
    const float* W2_1 = (const float*)d_in[14];
    const float* b2_1 = (const float*)d_in[15];
    const float* g1   = (const float*)d_in[16];
    const float* be1  = (const float*)d_in[17];
    const float* rm1  = (const float*)d_in[18];
    const float* rv1  = (const float*)d_in[19];
    float* out = (float*)d_out;

    cudaFuncSetAttribute(knn_kernel,
                         cudaFuncAttributeMaxDynamicSharedMemorySize, KNN_SMEM_BYTES);
    cudaFuncSetAttribute(gin_layer_kernel,
                         cudaFuncAttributeMaxDynamicSharedMemorySize, GIN_SMEM_BYTES);

    void *p_h0, *p_h1;
    cudaGetSymbolAddress(&p_h0, g_h0);
    cudaGetSymbolAddress(&p_h1, g_h1);

    knn_kernel<<<NB*(NP/KBLK), KBLK, KNN_SMEM_BYTES>>>(x);
    transfer_kernel<<<(NTOT*HDIM)/256, 256>>>(x, Wt, bt);

    gin_layer_kernel<<<NTOT/ROWS, LTHREADS, GIN_SMEM_BYTES>>>(
        (const float*)p_h0, W1_0, b1_0, W2_0, b2_0, g0, be0, rm0, rv0,
        (float*)p_h1, /*relu_out=*/1);

    gin_layer_kernel<<<NTOT/ROWS, LTHREADS, GIN_SMEM_BYTES>>>(
        (const float*)p_h1, W1_1, b1_1, W2_1, b2_1, g1, be1, rm1, rv1,
        out, /*relu_out=*/0);
}

// round 11
// speedup vs baseline: 2.6109x; 1.3558x over previous
#include <cuda_runtime.h>
#include <cuda_bf16.h>
#include <math.h>
#include <stdint.h>

#define NB   32
#define NP   2048
#define KNN  20
#define HDIM 128
#define HID  256
#define NTOT (NB*NP)
#define EPSBN 1e-5f

// ---------------- scratch (static device globals; no allocation) ----------------
__device__ int   g_nbr[NTOT*KNN];
__device__ float g_h0[(size_t)NTOT*HDIM];
__device__ float g_h1[(size_t)NTOT*HDIM];
// pre-split (bf16 hi/lo), pre-swizzled weights: [layer][half][hi=0/lo=1][128*128]
__device__ __nv_bfloat16 g_w1b[2][2][2][16384];
__device__ __nv_bfloat16 g_w2b[2][2][2][16384];

// ---------------- helpers -------------------------------------------------------
__device__ __forceinline__ uint32_t smem_u32(const void* p) {
    uint32_t a;
    asm("{ .reg .u64 t; cvta.to.shared.u64 t, %1; cvt.u32.u64 %0, t; }" : "=r"(a) : "l"(p));
    return a;
}
// pack two f32 -> bf16x2 (lower = first arg), rn rounding
__device__ __forceinline__ uint32_t pkbf(float lo, float hi) {
    uint32_t r; asm("cvt.rn.bf16x2.f32 %0, %1, %2;" : "=r"(r) : "f"(hi), "f"(lo)); return r;
}
__device__ __forceinline__ float bfhi(float v) {           // bf16-rounded value as f32
    return __bfloat162float(__float2bfloat16_rn(v));
}
// mma.sync m16n8k16 row.col f32.bf16.bf16.f32 (plain-sm_103-legal tensor path)
__device__ __forceinline__ void mma16816(float (&c)[4], const uint32_t (&a)[4],
                                         uint32_t b0, uint32_t b1) {
    asm volatile(
        "mma.sync.aligned.m16n8k16.row.col.f32.bf16.bf16.f32 "
        "{%0,%1,%2,%3}, {%4,%5,%6,%7}, {%8,%9}, {%0,%1,%2,%3};"
        : "+f"(c[0]), "+f"(c[1]), "+f"(c[2]), "+f"(c[3])
        : "r"(a[0]), "r"(a[1]), "r"(a[2]), "r"(a[3]), "r"(b0), "r"(b1));
}
// A frag (m16 x k16) from row-major swizzled bf16 [rows][128] tile
__device__ __forceinline__ void ldmA(uint32_t (&a)[4], uint32_t base, int m0, int k0, int lane) {
    int row = m0 + (lane & 15);
    int ch  = (k0 >> 3) + (lane >> 4);
    uint32_t addr = base + row*256 + (((ch ^ (row & 7)) & 15) << 4);
    asm volatile("ldmatrix.sync.aligned.m8n8.x4.shared.b16 {%0,%1,%2,%3}, [%4];"
                 : "=r"(a[0]), "=r"(a[1]), "=r"(a[2]), "=r"(a[3]) : "r"(addr));
}
// B frags (k16 x n16 -> two n8 tiles) from row-major swizzled bf16 [k][128] tile
__device__ __forceinline__ void ldmBt(uint32_t (&b)[4], uint32_t base, int k0, int n0, int lane) {
    int k = k0 + (lane & 7) + ((lane >> 3) & 1) * 8;
    int n = n0 + ((lane >> 4) & 1) * 8;
    uint32_t addr = base + k*256 + ((((n >> 3) ^ (k & 7)) & 15) << 4);
    asm volatile("ldmatrix.sync.aligned.m8n8.x4.trans.shared.b16 {%0,%1,%2,%3}, [%4];"
                 : "=r"(b[0]), "=r"(b[1]), "=r"(b[2]), "=r"(b[3]) : "r"(addr));
}

// ================================================================= kNN =========
// (unchanged from R8 760us win)
#define KBLK 128
#define KCAP 32
#define KNN_SMEM_BYTES (NP*16 + KCAP*KBLK*4)   // 49152
__global__ __launch_bounds__(KBLK)
void knn_kernel(const float* __restrict__ x)
{
    extern __shared__ float4 sc[];
    int* sbi = (int*)(sc + NP);
    const int b    = blockIdx.x >> 4;
    const int tile = blockIdx.x & 15;
    const int tid  = threadIdx.x;

    const float* xb = x + (size_t)b*NP*3;
    for (int i = tid; i < NP; i += KBLK) {
        float a0 = xb[i*3+0], a1 = xb[i*3+1], a2 = xb[i*3+2];
        sc[i] = make_float4(a0, a1, a2, a0*a0 + a1*a1 + a2*a2);
    }
    __syncthreads();

    const int q = tile*KBLK + tid;
    const float4 qc = sc[q];

    float d[KNN]; int id[KNN];
#pragma unroll
    for (int j = 0; j < KNN; j++) { d[j] = INFINITY; id[j] = -1; }
    float worst = INFINITY;
    int cnt = 0;

    for (int c0 = 0; c0 < NP; c0 += 4) {
#pragma unroll
        for (int u = 0; u < 4; u++) {
            int c = c0 + u;
            float4 cc = sc[c];
            float dot  = qc.x*cc.x + qc.y*cc.y + qc.z*cc.z;
            float dist = qc.w + cc.w - 2.0f*dot;
            if (dist < worst) { sbi[cnt*KBLK + tid] = c; cnt++; }
        }
        if (__any_sync(0xffffffffu, cnt >= KCAP-4)) {
            for (int j = 0; ; j++) {
                if (!__any_sync(0xffffffffu, j < cnt)) break;
                float dd = INFINITY; int ii = 0;
                if (j < cnt) {
                    ii = sbi[j*KBLK + tid];
                    float4 cc = sc[ii];
                    float dot = qc.x*cc.x + qc.y*cc.y + qc.z*cc.z;
                    dd = qc.w + cc.w - 2.0f*dot;
                }
                if (dd < worst) {
                    float vd = dd; int vi = ii;
#pragma unroll
                    for (int t = 0; t < KNN; t++) {
                        if (vd < d[t]) {
                            float td = d[t]; int ti = id[t];
                            d[t] = vd; id[t] = vi; vd = td; vi = ti;
                        }
                    }
                    worst = d[KNN-1];
                }
            }
            cnt = 0;
        }
    }
    for (int j = 0; ; j++) {
        if (!__any_sync(0xffffffffu, j < cnt)) break;
        float dd = INFINITY; int ii = 0;
        if (j < cnt) {
            ii = sbi[j*KBLK + tid];
            float4 cc = sc[ii];
            float dot = qc.x*cc.x + qc.y*cc.y + qc.z*cc.z;
            dd = qc.w + cc.w - 2.0f*dot;
        }
        if (dd < worst) {
            float vd = dd; int vi = ii;
#pragma unroll
            for (int t = 0; t < KNN; t++) {
                if (vd < d[t]) {
                    float td = d[t]; int ti = id[t];
                    d[t] = vd; id[t] = vi; vd = td; vi = ti;
                }
            }
            worst = d[KNN-1];
        }
    }

    int* outp = g_nbr + ((size_t)b*NP + q)*KNN;
#pragma unroll
    for (int j = 0; j < KNN; j++) outp[j] = b*NP + id[j];
}

// ============================================================ transfer =========
__global__ void transfer_kernel(const float* __restrict__ x,
                                const float* __restrict__ Wt,
                                const float* __restrict__ bt)
{
    int idx = blockIdx.x * blockDim.x + threadIdx.x;
    int n = idx >> 7, f = idx & (HDIM-1);
    float x0 = x[n*3+0], x1 = x[n*3+1], x2 = x[n*3+2];
    g_h0[idx] = bt[f] + x0*Wt[f] + x1*Wt[HDIM+f] + x2*Wt[2*HDIM+f];
}

// ============================================================ weight prep ======
// bf16 hi/lo split + XOR-chunk swizzle, tiled [128k][128n] per half.
__global__ void prep_w_kernel(const float* __restrict__ W1_0, const float* __restrict__ W2_0,
                              const float* __restrict__ W1_1, const float* __restrict__ W2_1)
{
    int idx = blockIdx.x * blockDim.x + threadIdx.x;   // 0..131071
    int layer = idx >> 16;
    int rem = idx & 65535;
    const float* W1 = layer ? W1_1 : W1_0;
    const float* W2 = layer ? W2_1 : W2_0;
    if (rem < 32768) {                       // W1 [k=128][n=256]
        int k = rem >> 8, n = rem & 255;
        float v = W1[k*HID + n];
        int h = n >> 7, nl = n & 127;
        int dst = k*128 + (((nl >> 3) ^ (k & 7)) << 3) + (nl & 7);
        __nv_bfloat16 hb = __float2bfloat16_rn(v);
        g_w1b[layer][h][0][dst] = hb;
        g_w1b[layer][h][1][dst] = __float2bfloat16_rn(v - __bfloat162float(hb));
    } else {                                 // W2 [K=256][n=128]
        int r2 = rem - 32768;
        int K = r2 >> 7, n = r2 & 127;
        float v = W2[K*HDIM + n];
        int h = K >> 7, kl = K & 127;
        int dst = kl*128 + (((n >> 3) ^ (kl & 7)) << 3) + (n & 7);
        __nv_bfloat16 hb = __float2bfloat16_rn(v);
        g_w2b[layer][h][0][dst] = hb;
        g_w2b[layer][h][1][dst] = __float2bfloat16_rn(v - __bfloat162float(hb));
    }
}

// ============================================================ GIN layer (mma.sync)
// Per block: 128 rows, 16 warps as 4x4 (wm, wn). bf16x3 split GEMMs:
// GEMM1 halves (N-chunks of 128) -> c1 regs -> bias+ReLU -> split to sT ->
// GEMM2 accumulate (K-half) into c2 regs -> BN -> store.
#define GT_THREADS 512
// smem bytes: b1[256]f @0, scale[128]f @1024, shift[128]f @1536,
// Ahi @2048(32K), Alo @34816, Thi @67584, Tlo @100352, Whi @133120, Wlo @165888
#define OFF_AHI  2048
#define OFF_ALO  (OFF_AHI + 32768)
#define OFF_THI  (OFF_ALO + 32768)
#define OFF_TLO  (OFF_THI + 32768)
#define OFF_WHI  (OFF_TLO + 32768)
#define OFF_WLO  (OFF_WHI + 32768)
#define GT_SMEM  (OFF_WLO + 32768)           // 198656

__global__ __launch_bounds__(GT_THREADS, 1)
void gin_mma_kernel(const float* __restrict__ hin, float* __restrict__ hout, int layer,
                    const float* __restrict__ b1v, const float* __restrict__ b2v,
                    const float* __restrict__ gw, const float* __restrict__ bb,
                    const float* __restrict__ rm, const float* __restrict__ rv,
                    int relu_out)
{
    extern __shared__ char smem[];
    const uint32_t smb = smem_u32(smem);
    const int tid  = threadIdx.x;
    const int wid  = tid >> 5;
    const int lane = tid & 31;
    const int wm   = wid >> 2;            // 0..3 -> M rows wm*32
    const int wn   = wid & 3;             // 0..3 -> N cols wn*32
    const int g    = lane >> 2;           // group row 0..7
    const int t4   = lane & 3;
    const int row0 = blockIdx.x * 128;

    float* s_b1    = (float*)(smem);
    float* s_scale = (float*)(smem + 1024);
    float* s_shift = (float*)(smem + 1536);
    int*   s_nbr   = (int*)(smem + OFF_WHI);   // overlay during gather only

    for (int i = tid; i < HID; i += GT_THREADS) s_b1[i] = b1v[i];
    if (tid < HDIM) {
        float sc = gw[tid] * rsqrtf(rv[tid] + EPSBN);
        s_scale[tid] = sc;
        s_shift[tid] = bb[tid] - sc * rm[tid];
    }
    for (int i = tid; i < 128*KNN; i += GT_THREADS)
        s_nbr[i] = g_nbr[(size_t)row0*KNN + i];
    __syncthreads();

    // ---- gather-max + bf16 hi/lo split into swizzled A ----
    for (int r = wid; r < 128; r += 16) {
        int row = row0 + r;
        float4 m = __ldg((const float4*)&hin[(size_t)row*HDIM + lane*4]);
#pragma unroll 4
        for (int k = 0; k < KNN; k++) {
            int nb = s_nbr[r*KNN + k];
            float4 v = __ldg((const float4*)&hin[(size_t)nb*HDIM + lane*4]);
            m.x = fmaxf(m.x, v.x); m.y = fmaxf(m.y, v.y);
            m.z = fmaxf(m.z, v.z); m.w = fmaxf(m.w, v.w);
        }
        float h0 = bfhi(m.x), h1 = bfhi(m.y), h2 = bfhi(m.z), h3 = bfhi(m.w);
        int ab = r*256 + ((((lane >> 1) ^ (r & 7)) & 15) << 4) + (lane & 1)*8;
        *(uint2*)(smem + OFF_AHI + ab) = make_uint2(pkbf(m.x, m.y), pkbf(m.z, m.w));
        *(uint2*)(smem + OFF_ALO + ab) =
            make_uint2(pkbf(m.x - h0, m.y - h1), pkbf(m.z - h2, m.w - h3));
    }
    __syncthreads();

    // ---- c2 accumulators (out tile 32x32), bias b2 folded in ----
    float c2[2][4][4];
#pragma unroll
    for (int mt = 0; mt < 2; mt++)
#pragma unroll
        for (int nt = 0; nt < 4; nt++) {
            int cb = wn*32 + nt*8 + 2*t4;
            c2[mt][nt][0] = b2v[cb];  c2[mt][nt][1] = b2v[cb+1];
            c2[mt][nt][2] = b2v[cb];  c2[mt][nt][3] = b2v[cb+1];
        }

    const uint32_t Ah = smb + OFF_AHI, Al = smb + OFF_ALO;
    const uint32_t Th = smb + OFF_THI, Tl = smb + OFF_TLO;
    const uint32_t Wh = smb + OFF_WHI, Wl = smb + OFF_WLO;

    for (int h = 0; h < 2; h++) {
        // ---- stage W1 half ----
        {
            const float4* sh = (const float4*)g_w1b[layer][h][0];
            const float4* sl = (const float4*)g_w1b[layer][h][1];
            float4* dh = (float4*)(smem + OFF_WHI);
            float4* dl = (float4*)(smem + OFF_WLO);
            for (int i = tid; i < 2048; i += GT_THREADS) { dh[i] = sh[i]; dl[i] = sl[i]; }
        }
        __syncthreads();

        // ---- GEMM1: c1 = A @ W1h (+b1), bf16x3 ----
        float c1[2][4][4];
#pragma unroll
        for (int mt = 0; mt < 2; mt++)
#pragma unroll
            for (int nt = 0; nt < 4; nt++) {
                int cb = h*128 + wn*32 + nt*8 + 2*t4;
                c1[mt][nt][0] = s_b1[cb];  c1[mt][nt][1] = s_b1[cb+1];
                c1[mt][nt][2] = s_b1[cb];  c1[mt][nt][3] = s_b1[cb+1];
            }
#pragma unroll
        for (int ks = 0; ks < 8; ks++) {
            uint32_t aH[2][4], aL[2][4];
            ldmA(aH[0], Ah, wm*32,      ks*16, lane);
            ldmA(aH[1], Ah, wm*32 + 16, ks*16, lane);
            ldmA(aL[0], Al, wm*32,      ks*16, lane);
            ldmA(aL[1], Al, wm*32 + 16, ks*16, lane);
#pragma unroll
            for (int np = 0; np < 2; np++) {
                uint32_t bh[4], bl[4];
                ldmBt(bh, Wh, ks*16, wn*32 + np*16, lane);
                ldmBt(bl, Wl, ks*16, wn*32 + np*16, lane);
#pragma unroll
                for (int mt = 0; mt < 2; mt++)
#pragma unroll
                    for (int n2 = 0; n2 < 2; n2++) {
                        int nt = np*2 + n2;
                        mma16816(c1[mt][nt], aH[mt], bh[n2*2], bh[n2*2+1]);
                        mma16816(c1[mt][nt], aL[mt], bh[n2*2], bh[n2*2+1]);
                        mma16816(c1[mt][nt], aH[mt], bl[n2*2], bl[n2*2+1]);
                    }
            }
        }

        // ---- t1 = relu(c1): split to sT (swizzled) ----
#pragma unroll
        for (int mt = 0; mt < 2; mt++)
#pragma unroll
            for (int nt = 0; nt < 4; nt++) {
                int r0 = wm*32 + mt*16 + g;
                int r1 = r0 + 8;
                int cl = wn*32 + nt*8 + 2*t4;
                float v0 = fmaxf(c1[mt][nt][0], 0.f), v1 = fmaxf(c1[mt][nt][1], 0.f);
                float v2 = fmaxf(c1[mt][nt][2], 0.f), v3 = fmaxf(c1[mt][nt][3], 0.f);
                float h0 = bfhi(v0), h1 = bfhi(v1), h2 = bfhi(v2), h3 = bfhi(v3);
                int by0 = r0*256 + ((((cl >> 3) ^ (r0 & 7)) & 15) << 4) + (cl & 7)*2;
                int by1 = r1*256 + ((((cl >> 3) ^ (r1 & 7)) & 15) << 4) + (cl & 7)*2;
                *(uint32_t*)(smem + OFF_THI + by0) = pkbf(v0, v1);
                *(uint32_t*)(smem + OFF_TLO + by0) = pkbf(v0 - h0, v1 - h1);
                *(uint32_t*)(smem + OFF_THI + by1) = pkbf(v2, v3);
                *(uint32_t*)(smem + OFF_TLO + by1) = pkbf(v2 - h2, v3 - h3);
            }
        __syncthreads();

        // ---- stage W2 half (overwrites W1 staging) ----
        {
            const float4* sh = (const float4*)g_w2b[layer][h][0];
            const float4* sl = (const float4*)g_w2b[layer][h][1];
            float4* dh = (float4*)(smem + OFF_WHI);
            float4* dl = (float4*)(smem + OFF_WLO);
            for (int i = tid; i < 2048; i += GT_THREADS) { dh[i] = sh[i]; dl[i] = sl[i]; }
        }
        __syncthreads();

        // ---- GEMM2: c2 += t1 @ W2h, bf16x3 ----
#pragma unroll
        for (int ks = 0; ks < 8; ks++) {
            uint32_t aH[2][4], aL[2][4];
            ldmA(aH[0], Th, wm*32,      ks*16, lane);
            ldmA(aH[1], Th, wm*32 + 16, ks*16, lane);
            ldmA(aL[0], Tl, wm*32,      ks*16, lane);
            ldmA(aL[1], Tl, wm*32 + 16, ks*16, lane);
#pragma unroll
            for (int np = 0; np < 2; np++) {
                uint32_t bh[4], bl[4];
                ldmBt(bh, Wh, ks*16, wn*32 + np*16, lane);
                ldmBt(bl, Wl, ks*16, wn*32 + np*16, lane);
#pragma unroll
                for (int mt = 0; mt < 2; mt++)
#pragma unroll
                    for (int n2 = 0; n2 < 2; n2++) {
                        int nt = np*2 + n2;
                        mma16816(c2[mt][nt], aH[mt], bh[n2*2], bh[n2*2+1]);
                        mma16816(c2[mt][nt], aL[mt], bh[n2*2], bh[n2*2+1]);
                        mma16816(c2[mt][nt], aH[mt], bl[n2*2], bl[n2*2+1]);
                    }
            }
        }
        __syncthreads();   // before next-half staging overwrites sW / GEMM1 rewrites sT
    }

    // ---- BN (+opt ReLU), direct STG.64 ----
#pragma unroll
    for (int mt = 0; mt < 2; mt++)
#pragma unroll
        for (int nt = 0; nt < 4; nt++) {
            int row = row0 + wm*32 + mt*16 + g;
            int col = wn*32 + nt*8 + 2*t4;
            float s0 = s_scale[col], s1 = s_scale[col+1];
            float t0 = s_shift[col], t1 = s_shift[col+1];
            float v0 = s0*c2[mt][nt][0] + t0, v1 = s1*c2[mt][nt][1] + t1;
            float v2 = s0*c2[mt][nt][2] + t0, v3 = s1*c2[mt][nt][3] + t1;
            if (relu_out) {
                v0 = fmaxf(v0, 0.f); v1 = fmaxf(v1, 0.f);
                v2 = fmaxf(v2, 0.f); v3 = fmaxf(v3, 0.f);
            }
            *(float2*)&hout[(size_t)row*HDIM + col]     = make_float2(v0, v1);
            *(float2*)&hout[(size_t)(row+8)*HDIM + col] = make_float2(v2, v3);
        }
}

// ================================================================ launch =======
extern "C" void kernel_launch(void* const* d_in, const int* in_sizes, int n_in,
                              void* d_out, int out_size)
{
    const float* x    = (const float*)d_in[0];
    const float* Wt   = (const float*)d_in[2];
    const float* bt   = (const float*)d_in[3];
    const float* W1_0 = (const float*)d_in[4];
    const float* b1_0 = (const float*)d_in[5];
    const float* W2_0 = (const float*)d_in[6];
    const float* b2_0 = (const float*)d_in[7];
    const float* g0   = (const float*)d_in[8];
    const float* be0  = (const float*)d_in[9];
    const float* rm0  = (const float*)d_in[10];
    const float* rv0  = (const float*)d_in[11];
    const float* W1_1 = (const float*)d_in[12];
    const float* b1_1 = (const float*)d_in[13];
    const float* W2_1 = (const float*)d_in[14];
    const float* b2_1 = (const float*)d_in[15];
    const float* g1   = (const float*)d_in[16];
    const float* be1  = (const float*)d_in[17];
    const float* rm1  = (const float*)d_in[18];
    const float* rv1  = (const float*)d_in[19];
    float* out = (float*)d_out;

    cudaFuncSetAttribute(knn_kernel,
                         cudaFuncAttributeMaxDynamicSharedMemorySize, KNN_SMEM_BYTES);
    cudaFuncSetAttribute(gin_mma_kernel,
                         cudaFuncAttributeMaxDynamicSharedMemorySize, GT_SMEM);

    void *p_h0, *p_h1;
    cudaGetSymbolAddress(&p_h0, g_h0);
    cudaGetSymbolAddress(&p_h1, g_h1);

    prep_w_kernel<<<512, 256>>>(W1_0, W2_0, W1_1, W2_1);
    knn_kernel<<<NB*(NP/KBLK), KBLK, KNN_SMEM_BYTES>>>(x);
    transfer_kernel<<<(NTOT*HDIM)/256, 256>>>(x, Wt, bt);

    gin_mma_kernel<<<NTOT/128, GT_THREADS, GT_SMEM>>>(
        (const float*)p_h0, (float*)p_h1, 0,
        b1_0, b2_0, g0, be0, rm0, rv0, /*relu_out=*/1);

    gin_mma_kernel<<<NTOT/128, GT_THREADS, GT_SMEM>>>(
        (const float*)p_h1, out, 1,
        b1_1, b2_1, g1, be1, rm1, rv1, /*relu_out=*/0);
}